// round 4
// baseline (speedup 1.0000x reference)
#include <cuda_runtime.h>

#define BB 32
#define TT 2048
#define CC 2048
#define EE 64
#define SEG 16
#define TCHUNK (TT / SEG)          // 128
#define C4 (CC / 4)                // 512

#define BTE (BB * TT * EE)         // 4194304
#define FB_OFF  BTE                // 4194304
#define LOG_OFF (BTE + 1)          // 4194305
#define MASK_OFF (BTE + 1 + BB * EE) // 4196353  (not 16B aligned -> scalar stores)

// Scratch (no cudaMalloc allowed)
__device__ float g_partials[SEG * BB * CC];  // 2 MB
__device__ float g_probs_seq[BB * EE];
__device__ float g_mask_seq[BB * EE];

// ---------------------------------------------------------------------------
// Kernel 1: partial sums of hidden_states over T (split into SEG chunks).
// grid = (C4/256=2, B=32, SEG=16) = 1024 blocks x 256 threads. float4 loads.
// Also initializes the fallback_count slot to 0 (k2 atomically increments it).
// ---------------------------------------------------------------------------
__global__ void k1_partial_sums(const float* __restrict__ hs, float* __restrict__ out) {
    if (blockIdx.x == 0 && blockIdx.y == 0 && blockIdx.z == 0 && threadIdx.x == 0)
        out[FB_OFF] = 0.0f;

    const int c4  = blockIdx.x * 256 + threadIdx.x;   // 0..511
    const int b   = blockIdx.y;
    const int seg = blockIdx.z;

    const float4* __restrict__ hs4 = (const float4*)hs;
    size_t base = ((size_t)b * TT + (size_t)seg * TCHUNK) * C4 + (size_t)c4;

    float4 acc = make_float4(0.f, 0.f, 0.f, 0.f);
#pragma unroll 8
    for (int t = 0; t < TCHUNK; ++t) {
        float4 v = hs4[base + (size_t)t * C4];
        acc.x += v.x; acc.y += v.y; acc.z += v.z; acc.w += v.w;
    }
    ((float4*)g_partials)[((size_t)seg * BB + b) * C4 + c4] = acc;
}

// ---------------------------------------------------------------------------
// Kernel 2: per-batch-row gating. One block per b (32 blocks, 256 threads).
// ---------------------------------------------------------------------------
__global__ void k2_gating(const float* __restrict__ sim, const float* __restrict__ gates,
                          float* __restrict__ out) {
    __shared__ float rep[CC];          // mean representation, 8 KB
    __shared__ float red[256];
    __shared__ float logits_s[EE];
    __shared__ float mask_s[EE];
    __shared__ float sm_nrep;
    __shared__ int   sm_inactive;
    __shared__ float sm_max, sm_sum;

    const int b = blockIdx.x;
    const int tid = threadIdx.x;

    // --- Step A: finish mean over T, accumulate ||rep||^2 ---
    float sumsq = 0.f;
    for (int c = tid; c < CC; c += 256) {
        float s = 0.f;
#pragma unroll
        for (int p = 0; p < SEG; ++p)
            s += g_partials[(size_t)p * BB * CC + (size_t)b * CC + c];
        float r = s * (1.0f / TT);
        rep[c] = r;
        sumsq += r * r;
    }
    red[tid] = sumsq;
    __syncthreads();
    for (int ofs = 128; ofs > 0; ofs >>= 1) {
        if (tid < ofs) red[tid] += red[tid + ofs];
        __syncthreads();
    }
    if (tid == 0) sm_nrep = sqrtf(red[0]);
    __syncthreads();
    const float nrep = fmaxf(sm_nrep, 1e-12f);

    // --- Step B: cosine similarity per expert (one warp handles 8 experts) ---
    const int warp = tid >> 5, lane = tid & 31;
#pragma unroll
    for (int k = 0; k < 8; ++k) {
        int e = warp * 8 + k;
        float dot = 0.f, ss = 0.f;
        for (int c = lane; c < CC; c += 32) {
            float sv = sim[(size_t)c * EE + e];
            dot += rep[c] * sv;
            ss  += sv * sv;
        }
#pragma unroll
        for (int o = 16; o > 0; o >>= 1) {
            dot += __shfl_down_sync(0xffffffffu, dot, o);
            ss  += __shfl_down_sync(0xffffffffu, ss,  o);
        }
        if (lane == 0) {
            float ncol = fmaxf(sqrtf(ss), 1e-12f);
            float aff  = dot / (nrep * ncol);
            float g    = gates[e];
            float sig  = 1.0f / (1.0f + __expf(-g));
            logits_s[e] = aff - sig;
        }
    }
    __syncthreads();

    // --- Step C: activity count (tiny, thread 0) ---
    if (tid == 0) {
        int na = 0;
        for (int e = 0; e < EE; ++e) na += (logits_s[e] > 0.f) ? 1 : 0;
        sm_inactive = (na == 0) ? 1 : 0;
    }
    __syncthreads();
    const int inactive = sm_inactive;

    // --- Step D: mask (hard threshold, or top-32 fallback with lax.top_k
    //     tie semantics: stable, lowest index wins among equals) ---
    if (tid < EE) {
        float l = logits_s[tid];
        float m;
        if (!inactive) {
            m = (l > 0.f) ? 1.f : 0.f;
        } else {
            int rank = 0;
            for (int j = 0; j < EE; ++j) {
                float lj = logits_s[j];
                rank += ((lj > l) || (lj == l && j < tid)) ? 1 : 0;
            }
            m = (rank < (EE / 2)) ? 1.f : 0.f;
        }
        mask_s[tid] = m;
    }
    __syncthreads();

    // --- Step E: masked softmax stats (64 elems, thread 0 is fine) ---
    if (tid == 0) {
        float mx = -3.402823466e+38f;
        for (int e = 0; e < EE; ++e)
            if (mask_s[e] > 0.f) mx = fmaxf(mx, fmaxf(logits_s[e], 0.f));
        float sum = 0.f;
        for (int e = 0; e < EE; ++e)
            if (mask_s[e] > 0.f) sum += __expf(fmaxf(logits_s[e], 0.f) - mx);
        sm_max = mx;
        sm_sum = sum;
        if (inactive) atomicAdd(&out[FB_OFF], 1.0f);  // integer-valued -> deterministic
    }
    __syncthreads();

    // --- Step F: write per-row results ---
    if (tid < EE) {
        float l = logits_s[tid];
        float gated = fmaxf(l, 0.f);
        float p = (mask_s[tid] > 0.f) ? (__expf(gated - sm_max) / sm_sum) : 0.f;
        g_probs_seq[b * EE + tid] = p;
        g_mask_seq[b * EE + tid]  = mask_s[tid];
        out[LOG_OFF + b * EE + tid] = l;
    }
}

// ---------------------------------------------------------------------------
// Kernel 3: broadcast [B,E] probs & mask over T into [B,T,E] outputs.
// probs region is 16B-aligned -> float4 stores; mask region base %4==1 -> scalar.
// grid = 4096 x 256 threads, one thread per 4 elements of the [B,T,E] cube.
// ---------------------------------------------------------------------------
__global__ void k3_broadcast(float* __restrict__ out) {
    size_t idx = (size_t)blockIdx.x * blockDim.x + threadIdx.x;  // < BTE/4
    const int E4 = EE / 4;                 // 16
    int e4 = (int)(idx & (E4 - 1));
    size_t bt = idx >> 4;                  // 0..B*T-1
    int b = (int)(bt >> 11);               // bt / T, T = 2048

    float4 p = ((const float4*)g_probs_seq)[b * E4 + e4];
    float4 m = ((const float4*)g_mask_seq)[b * E4 + e4];

    ((float4*)out)[idx] = p;

    float* mdst = out + MASK_OFF + idx * 4;
    mdst[0] = m.x; mdst[1] = m.y; mdst[2] = m.z; mdst[3] = m.w;
}

// ---------------------------------------------------------------------------
extern "C" void kernel_launch(void* const* d_in, const int* in_sizes, int n_in,
                              void* d_out, int out_size) {
    const float* hs    = (const float*)d_in[0];
    const float* sim   = (const float*)d_in[1];
    const float* gates = (const float*)d_in[2];
    float* out = (float*)d_out;

    k1_partial_sums<<<dim3(C4 / 256, BB, SEG), 256>>>(hs, out);
    k2_gating<<<BB, 256>>>(sim, gates, out);
    k3_broadcast<<<(BTE / 4) / 256, 256>>>(out);
}

// round 5
// speedup vs baseline: 1.2787x; 1.2787x over previous
#include <cuda_runtime.h>

#define BB 32
#define TT 2048
#define CC 2048
#define EE 64
#define SEG 16
#define TCHUNK (TT / SEG)          // 128
#define C4 (CC / 4)                // 512

#define BTE (BB * TT * EE)         // 4194304
#define FB_OFF  BTE                // 4194304
#define LOG_OFF (BTE + 1)          // 4194305
#define MASK_OFF (BTE + 1 + BB * EE) // 4196353  (not 16B aligned -> scalar stores)

// Scratch (no cudaMalloc allowed)
__device__ float g_partials[SEG * BB * CC];  // 2 MB
__device__ float g_probs_seq[BB * EE];
__device__ float g_mask_seq[BB * EE];

// ---------------------------------------------------------------------------
// Kernel 1: partial sums of hidden_states over T (split into SEG chunks).
// grid = (C4/256=2, B=32, SEG=16) = 1024 blocks x 256 threads. float4 loads.
// Also initializes the fallback_count slot to 0 (k2 atomically increments it).
// Measured at 86% DRAM / 6.8 TB/s — at roofline; unchanged.
// ---------------------------------------------------------------------------
__global__ void k1_partial_sums(const float* __restrict__ hs, float* __restrict__ out) {
    if (blockIdx.x == 0 && blockIdx.y == 0 && blockIdx.z == 0 && threadIdx.x == 0)
        out[FB_OFF] = 0.0f;

    const int c4  = blockIdx.x * 256 + threadIdx.x;   // 0..511
    const int b   = blockIdx.y;
    const int seg = blockIdx.z;

    const float4* __restrict__ hs4 = (const float4*)hs;
    size_t base = ((size_t)b * TT + (size_t)seg * TCHUNK) * C4 + (size_t)c4;

    float4 acc = make_float4(0.f, 0.f, 0.f, 0.f);
#pragma unroll 8
    for (int t = 0; t < TCHUNK; ++t) {
        float4 v = hs4[base + (size_t)t * C4];
        acc.x += v.x; acc.y += v.y; acc.z += v.z; acc.w += v.w;
    }
    ((float4*)g_partials)[((size_t)seg * BB + b) * C4 + c4] = acc;
}

// ---------------------------------------------------------------------------
// Kernel 2: per-batch-row gating. One block per b (32 blocks, 256 threads).
// REWORKED: lane -> expert mapping for sim reads (coalesced: 64 consecutive
// experts for fixed c = 256 contiguous bytes), c split across 4 groups.
// Cuts sim L2 traffic 32x vs the strided version.
// ---------------------------------------------------------------------------
__global__ void k2_gating(const float* __restrict__ sim, const float* __restrict__ gates,
                          float* __restrict__ out) {
    __shared__ float rep[CC];          // mean representation, 8 KB
    __shared__ float red[256];
    __shared__ float dots[4][EE];
    __shared__ float sss[4][EE];
    __shared__ float logits_s[EE];
    __shared__ float mask_s[EE];
    __shared__ float sm_nrep;
    __shared__ int   sm_inactive;
    __shared__ float sm_max, sm_sum;

    const int b = blockIdx.x;
    const int tid = threadIdx.x;

    // --- Step A: finish mean over T, accumulate ||rep||^2 ---
    float sumsq = 0.f;
    for (int c = tid; c < CC; c += 256) {
        float s = 0.f;
#pragma unroll
        for (int p = 0; p < SEG; ++p)
            s += g_partials[(size_t)p * BB * CC + (size_t)b * CC + c];
        float r = s * (1.0f / TT);
        rep[c] = r;
        sumsq += r * r;
    }
    red[tid] = sumsq;
    __syncthreads();
    for (int ofs = 128; ofs > 0; ofs >>= 1) {
        if (tid < ofs) red[tid] += red[tid + ofs];
        __syncthreads();
    }
    if (tid == 0) sm_nrep = sqrtf(red[0]);
    __syncthreads();
    const float nrep = fmaxf(sm_nrep, 1e-12f);

    // --- Step B: cosine similarity, coalesced over experts ---
    {
        const int e  = tid & (EE - 1);   // 0..63 (consecutive -> coalesced sim loads)
        const int cg = tid >> 6;         // 0..3 c-group
        float dot = 0.f, ss = 0.f;
#pragma unroll 8
        for (int c = cg; c < CC; c += 4) {
            float sv = sim[(size_t)c * EE + e];
            dot = fmaf(rep[c], sv, dot); // rep[c] uniform across sub-warp -> LDS broadcast
            ss  = fmaf(sv, sv, ss);
        }
        dots[cg][e] = dot;
        sss[cg][e]  = ss;
    }
    __syncthreads();

    if (tid < EE) {
        float dot = dots[0][tid] + dots[1][tid] + dots[2][tid] + dots[3][tid];
        float ss  = sss[0][tid]  + sss[1][tid]  + sss[2][tid]  + sss[3][tid];
        float ncol = fmaxf(sqrtf(ss), 1e-12f);
        float aff  = dot / (nrep * ncol);
        float g    = gates[tid];
        float sig  = 1.0f / (1.0f + __expf(-g));
        logits_s[tid] = aff - sig;
    }
    __syncthreads();

    // --- Step C: activity count ---
    if (tid == 0) {
        int na = 0;
        for (int e = 0; e < EE; ++e) na += (logits_s[e] > 0.f) ? 1 : 0;
        sm_inactive = (na == 0) ? 1 : 0;
    }
    __syncthreads();
    const int inactive = sm_inactive;

    // --- Step D: mask (hard threshold, or top-32 fallback with lax.top_k
    //     tie semantics: stable, lowest index wins among equals) ---
    if (tid < EE) {
        float l = logits_s[tid];
        float m;
        if (!inactive) {
            m = (l > 0.f) ? 1.f : 0.f;
        } else {
            int rank = 0;
            for (int j = 0; j < EE; ++j) {
                float lj = logits_s[j];
                rank += ((lj > l) || (lj == l && j < tid)) ? 1 : 0;
            }
            m = (rank < (EE / 2)) ? 1.f : 0.f;
        }
        mask_s[tid] = m;
    }
    __syncthreads();

    // --- Step E: masked softmax stats (64 elems, thread 0) ---
    if (tid == 0) {
        float mx = -3.402823466e+38f;
        for (int e = 0; e < EE; ++e)
            if (mask_s[e] > 0.f) mx = fmaxf(mx, fmaxf(logits_s[e], 0.f));
        float sum = 0.f;
        for (int e = 0; e < EE; ++e)
            if (mask_s[e] > 0.f) sum += __expf(fmaxf(logits_s[e], 0.f) - mx);
        sm_max = mx;
        sm_sum = sum;
        if (inactive) atomicAdd(&out[FB_OFF], 1.0f);  // integer-valued -> deterministic
    }
    __syncthreads();

    // --- Step F: write per-row results ---
    if (tid < EE) {
        float l = logits_s[tid];
        float gated = fmaxf(l, 0.f);
        float p = (mask_s[tid] > 0.f) ? (__expf(gated - sm_max) / sm_sum) : 0.f;
        g_probs_seq[b * EE + tid] = p;
        g_mask_seq[b * EE + tid]  = mask_s[tid];
        out[LOG_OFF + b * EE + tid] = l;
    }
}

// ---------------------------------------------------------------------------
// Kernel 3: broadcast [B,E] probs & mask over T into [B,T,E] outputs.
// probs region is 16B-aligned -> float4 stores; mask region base %4==1 -> scalar.
// grid = 4096 x 256 threads, one thread per 4 elements of the [B,T,E] cube.
// ---------------------------------------------------------------------------
__global__ void k3_broadcast(float* __restrict__ out) {
    size_t idx = (size_t)blockIdx.x * blockDim.x + threadIdx.x;  // < BTE/4
    const int E4 = EE / 4;                 // 16
    int e4 = (int)(idx & (E4 - 1));
    size_t bt = idx >> 4;                  // 0..B*T-1
    int b = (int)(bt >> 11);               // bt / T, T = 2048

    float4 p = ((const float4*)g_probs_seq)[b * E4 + e4];
    float4 m = ((const float4*)g_mask_seq)[b * E4 + e4];

    ((float4*)out)[idx] = p;

    float* mdst = out + MASK_OFF + idx * 4;
    mdst[0] = m.x; mdst[1] = m.y; mdst[2] = m.z; mdst[3] = m.w;
}

// ---------------------------------------------------------------------------
extern "C" void kernel_launch(void* const* d_in, const int* in_sizes, int n_in,
                              void* d_out, int out_size) {
    const float* hs    = (const float*)d_in[0];
    const float* sim   = (const float*)d_in[1];
    const float* gates = (const float*)d_in[2];
    float* out = (float*)d_out;

    k1_partial_sums<<<dim3(C4 / 256, BB, SEG), 256>>>(hs, out);
    k2_gating<<<BB, 256>>>(sim, gates, out);
    k3_broadcast<<<(BTE / 4) / 256, 256>>>(out);
}

// round 6
// speedup vs baseline: 1.3275x; 1.0382x over previous
#include <cuda_runtime.h>

#define BB 32
#define TT 2048
#define CC 2048
#define EE 64
#define SEG 16
#define TCHUNK (TT / SEG)          // 128
#define C4 (CC / 4)                // 512
#define E4N (EE / 4)               // 16

#define BTE (BB * TT * EE)         // 4194304 = 2^22
#define FB_OFF  BTE                // 4194304
#define LOG_OFF (BTE + 1)          // 4194305
#define MASK_OFF (BTE + 1 + BB * EE) // 4196353 (odd base -> coalesced scalar passes)

// Scratch (no cudaMalloc allowed)
__device__ float g_partials[SEG * BB * CC];  // 2 MB
__device__ float g_probs_seq[BB * EE];
__device__ float g_mask_seq[BB * EE];

// ---------------------------------------------------------------------------
// Kernel 1: partial sums of hidden_states over T (split into SEG chunks).
// Measured 86.6% DRAM / 6.86 TB/s = at the LTS chip cap. Unchanged.
// ---------------------------------------------------------------------------
__global__ void k1_partial_sums(const float* __restrict__ hs, float* __restrict__ out) {
    if (blockIdx.x == 0 && blockIdx.y == 0 && blockIdx.z == 0 && threadIdx.x == 0)
        out[FB_OFF] = 0.0f;

    const int c4  = blockIdx.x * 256 + threadIdx.x;   // 0..511
    const int b   = blockIdx.y;
    const int seg = blockIdx.z;

    const float4* __restrict__ hs4 = (const float4*)hs;
    size_t base = ((size_t)b * TT + (size_t)seg * TCHUNK) * C4 + (size_t)c4;

    float4 acc = make_float4(0.f, 0.f, 0.f, 0.f);
#pragma unroll 8
    for (int t = 0; t < TCHUNK; ++t) {
        float4 v = hs4[base + (size_t)t * C4];
        acc.x += v.x; acc.y += v.y; acc.z += v.z; acc.w += v.w;
    }
    ((float4*)g_partials)[((size_t)seg * BB + b) * C4 + c4] = acc;
}

// ---------------------------------------------------------------------------
// Kernel 2: per-batch-row gating. One block per b (32 blocks, 256 threads).
// Vectorized: float4 partial reduction + float4 sim loads (4x fewer mem ops).
// ---------------------------------------------------------------------------
__global__ void k2_gating(const float* __restrict__ sim, const float* __restrict__ gates,
                          float* __restrict__ out) {
    __shared__ float rep[CC];          // mean representation, 8 KB
    __shared__ float red[256];
    __shared__ float dots[16][EE];     // 4 KB
    __shared__ float sss[16][EE];      // 4 KB
    __shared__ float logits_s[EE];
    __shared__ float mask_s[EE];
    __shared__ float sm_nrep;
    __shared__ int   sm_inactive;
    __shared__ float sm_max, sm_sum;

    const int b = blockIdx.x;
    const int tid = threadIdx.x;

    // --- Step A: finish mean over T (float4), accumulate ||rep||^2 ---
    float sumsq = 0.f;
    const float4* __restrict__ gp4 = (const float4*)g_partials;
#pragma unroll
    for (int it = 0; it < 2; ++it) {
        int c4 = tid + it * 256;       // 0..511
        float4 s = make_float4(0.f, 0.f, 0.f, 0.f);
#pragma unroll
        for (int p = 0; p < SEG; ++p) {
            float4 v = gp4[((size_t)p * BB + b) * C4 + c4];
            s.x += v.x; s.y += v.y; s.z += v.z; s.w += v.w;
        }
        const float inv = 1.0f / TT;
        s.x *= inv; s.y *= inv; s.z *= inv; s.w *= inv;
        ((float4*)rep)[c4] = s;
        sumsq += s.x * s.x + s.y * s.y + s.z * s.z + s.w * s.w;
    }
    red[tid] = sumsq;
    __syncthreads();
    for (int ofs = 128; ofs > 0; ofs >>= 1) {
        if (tid < ofs) red[tid] += red[tid + ofs];
        __syncthreads();
    }
    if (tid == 0) sm_nrep = sqrtf(red[0]);
    __syncthreads();
    const float nrep = fmaxf(sm_nrep, 1e-12f);

    // --- Step B: cosine similarity, float4 over experts ---
    {
        const int e4 = tid & (E4N - 1);   // 0..15 -> experts 4*e4..4*e4+3
        const int cg = tid >> 4;          // 0..15 c-group
        const float4* __restrict__ sim4 = (const float4*)sim;
        float4 dot = make_float4(0.f, 0.f, 0.f, 0.f);
        float4 ss  = make_float4(0.f, 0.f, 0.f, 0.f);
#pragma unroll 8
        for (int c = cg; c < CC; c += 16) {
            float4 sv = sim4[(size_t)c * E4N + e4];
            float r = rep[c];
            dot.x = fmaf(r, sv.x, dot.x); dot.y = fmaf(r, sv.y, dot.y);
            dot.z = fmaf(r, sv.z, dot.z); dot.w = fmaf(r, sv.w, dot.w);
            ss.x = fmaf(sv.x, sv.x, ss.x); ss.y = fmaf(sv.y, sv.y, ss.y);
            ss.z = fmaf(sv.z, sv.z, ss.z); ss.w = fmaf(sv.w, sv.w, ss.w);
        }
        dots[cg][e4 * 4 + 0] = dot.x; dots[cg][e4 * 4 + 1] = dot.y;
        dots[cg][e4 * 4 + 2] = dot.z; dots[cg][e4 * 4 + 3] = dot.w;
        sss[cg][e4 * 4 + 0] = ss.x; sss[cg][e4 * 4 + 1] = ss.y;
        sss[cg][e4 * 4 + 2] = ss.z; sss[cg][e4 * 4 + 3] = ss.w;
    }
    __syncthreads();

    if (tid < EE) {
        float dot = 0.f, ss = 0.f;
#pragma unroll
        for (int g = 0; g < 16; ++g) { dot += dots[g][tid]; ss += sss[g][tid]; }
        float ncol = fmaxf(sqrtf(ss), 1e-12f);
        float aff  = dot / (nrep * ncol);
        float gv   = gates[tid];
        float sig  = 1.0f / (1.0f + __expf(-gv));
        logits_s[tid] = aff - sig;
    }
    __syncthreads();

    // --- Step C: activity count ---
    if (tid == 0) {
        int na = 0;
        for (int e = 0; e < EE; ++e) na += (logits_s[e] > 0.f) ? 1 : 0;
        sm_inactive = (na == 0) ? 1 : 0;
    }
    __syncthreads();
    const int inactive = sm_inactive;

    // --- Step D: mask (hard threshold, or top-32 fallback with lax.top_k
    //     tie semantics: stable, lowest index wins among equals) ---
    if (tid < EE) {
        float l = logits_s[tid];
        float m;
        if (!inactive) {
            m = (l > 0.f) ? 1.f : 0.f;
        } else {
            int rank = 0;
            for (int j = 0; j < EE; ++j) {
                float lj = logits_s[j];
                rank += ((lj > l) || (lj == l && j < tid)) ? 1 : 0;
            }
            m = (rank < (EE / 2)) ? 1.f : 0.f;
        }
        mask_s[tid] = m;
    }
    __syncthreads();

    // --- Step E: masked softmax stats ---
    if (tid == 0) {
        float mx = -3.402823466e+38f;
        for (int e = 0; e < EE; ++e)
            if (mask_s[e] > 0.f) mx = fmaxf(mx, fmaxf(logits_s[e], 0.f));
        float sum = 0.f;
        for (int e = 0; e < EE; ++e)
            if (mask_s[e] > 0.f) sum += __expf(fmaxf(logits_s[e], 0.f) - mx);
        sm_max = mx;
        sm_sum = sum;
        if (inactive) atomicAdd(&out[FB_OFF], 1.0f);  // integer-valued -> deterministic
    }
    __syncthreads();

    // --- Step F: write per-row results ---
    if (tid < EE) {
        float l = logits_s[tid];
        float gated = fmaxf(l, 0.f);
        float p = (mask_s[tid] > 0.f) ? (__expf(gated - sm_max) / sm_sum) : 0.f;
        g_probs_seq[b * EE + tid] = p;
        g_mask_seq[b * EE + tid]  = mask_s[tid];
        out[LOG_OFF + b * EE + tid] = l;
    }
}

// ---------------------------------------------------------------------------
// Kernel 3: broadcast [B,E] probs & mask over T into [B,T,E] outputs.
// probs: float4 stores (16B-aligned region).
// mask:  4 grid-stride scalar passes -> consecutive lanes hit consecutive
//        addresses = fully coalesced 128B/warp stores despite odd base.
// ---------------------------------------------------------------------------
__global__ void k3_broadcast(float* __restrict__ out) {
    const size_t idx = (size_t)blockIdx.x * blockDim.x + threadIdx.x;  // < BTE/4

    // probs (float4): idx indexes [B,T,E] in float4 units
    {
        int e4 = (int)(idx & (E4N - 1));
        int b  = (int)(idx >> 15);         // idx / (T*E/4) = idx / 32768
        float4 p = __ldg(&((const float4*)g_probs_seq)[b * E4N + e4]);
        ((float4*)out)[idx] = p;
    }

    // mask (scalar, 4 coalesced passes)
#pragma unroll
    for (int pass = 0; pass < 4; ++pass) {
        size_t gm = idx + (size_t)pass * (BTE / 4);   // < BTE, consecutive per warp
        int e = (int)(gm & (EE - 1));
        int b = (int)(gm >> 17);                      // gm / (T*E), T*E = 2^17
        out[MASK_OFF + gm] = __ldg(&g_mask_seq[b * EE + e]);
    }
}

// ---------------------------------------------------------------------------
extern "C" void kernel_launch(void* const* d_in, const int* in_sizes, int n_in,
                              void* d_out, int out_size) {
    const float* hs    = (const float*)d_in[0];
    const float* sim   = (const float*)d_in[1];
    const float* gates = (const float*)d_in[2];
    float* out = (float*)d_out;

    k1_partial_sums<<<dim3(C4 / 256, BB, SEG), 256>>>(hs, out);
    k2_gating<<<BB, 256>>>(sim, gates, out);
    k3_broadcast<<<(BTE / 4) / 256, 256>>>(out);
}

// round 7
// speedup vs baseline: 1.5703x; 1.1829x over previous
#include <cuda_runtime.h>

#define BB 32
#define TT 2048
#define CC 2048
#define EE 64
#define SEG 16
#define TCHUNK (TT / SEG)          // 128
#define C4 (CC / 4)                // 512
#define E4N (EE / 4)               // 16
#define TQ 128                     // t-rows per k23 block

#define BTE (BB * TT * EE)         // 4194304 = 2^22
#define FB_OFF  BTE                // 4194304
#define LOG_OFF (BTE + 1)          // 4194305
#define MASK_OFF (BTE + 1 + BB * EE) // 4196353 (== 1 mod 4)

// Scratch (no cudaMalloc allowed)
__device__ float g_partials[SEG * BB * CC];  // 2 MB
__device__ float g_probs_seq[BB * EE];
__device__ float g_mask_seq[BB * EE];
__device__ volatile int g_flag[BB];

// ---------------------------------------------------------------------------
// Kernel 1: partial sums of hidden_states over T (split into SEG chunks).
// Measured 86% DRAM / 6.8 TB/s (LTS/HBM cap). __ldcs: hs is stream-once,
// don't allocate 512 MB through L2. Also resets fallback slot + flags.
// ---------------------------------------------------------------------------
__global__ void k1_partial_sums(const float* __restrict__ hs, float* __restrict__ out) {
    if (blockIdx.x == 0 && blockIdx.y == 0 && blockIdx.z == 0) {
        if (threadIdx.x == 0) out[FB_OFF] = 0.0f;
        if (threadIdx.x < BB) g_flag[threadIdx.x] = 0;
    }

    const int c4  = blockIdx.x * 256 + threadIdx.x;   // 0..511
    const int b   = blockIdx.y;
    const int seg = blockIdx.z;

    const float4* __restrict__ hs4 = (const float4*)hs;
    size_t base = ((size_t)b * TT + (size_t)seg * TCHUNK) * C4 + (size_t)c4;

    float4 acc = make_float4(0.f, 0.f, 0.f, 0.f);
#pragma unroll 8
    for (int t = 0; t < TCHUNK; ++t) {
        float4 v = __ldcs(&hs4[base + (size_t)t * C4]);
        acc.x += v.x; acc.y += v.y; acc.z += v.z; acc.w += v.w;
    }
    ((float4*)g_partials)[((size_t)seg * BB + b) * C4 + c4] = acc;
}

// ---------------------------------------------------------------------------
// Kernel 2+3 fused. grid = (BB, TT/TQ) = (32, 16), 256 threads.
// Block (b, 0): computes gating for b, publishes via g_flag[b], then does
// its own broadcast chunk. Blocks (b, y>0): spin on g_flag[b], then broadcast.
// Producers are bids 0..31 -> scheduled in wave 1 -> deadlock-free.
// ---------------------------------------------------------------------------
__global__ void k23_gating_broadcast(const float* __restrict__ sim,
                                     const float* __restrict__ gates,
                                     float* __restrict__ out) {
    __shared__ float rep[CC];          // 8 KB (producer only)
    __shared__ float red[256];
    __shared__ float dots[16][EE];     // 4 KB
    __shared__ float sss[16][EE];      // 4 KB
    __shared__ float logits_s[EE];
    __shared__ float msk[EE];
    __shared__ float sm_nrep;
    __shared__ int   sm_inactive;
    __shared__ float sm_max, sm_sum;

    const int b   = blockIdx.x;
    const int yc  = blockIdx.y;
    const int tid = threadIdx.x;

    if (yc == 0) {
        // ================= gating (producer) =================
        // --- Step A: finish mean over T (float4), accumulate ||rep||^2 ---
        float sumsq = 0.f;
        const float4* __restrict__ gp4 = (const float4*)g_partials;
#pragma unroll
        for (int it = 0; it < 2; ++it) {
            int c4 = tid + it * 256;
            float4 s = make_float4(0.f, 0.f, 0.f, 0.f);
#pragma unroll
            for (int p = 0; p < SEG; ++p) {
                float4 v = gp4[((size_t)p * BB + b) * C4 + c4];
                s.x += v.x; s.y += v.y; s.z += v.z; s.w += v.w;
            }
            const float inv = 1.0f / TT;
            s.x *= inv; s.y *= inv; s.z *= inv; s.w *= inv;
            ((float4*)rep)[c4] = s;
            sumsq += s.x * s.x + s.y * s.y + s.z * s.z + s.w * s.w;
        }
        red[tid] = sumsq;
        __syncthreads();
        for (int ofs = 128; ofs > 0; ofs >>= 1) {
            if (tid < ofs) red[tid] += red[tid + ofs];
            __syncthreads();
        }
        if (tid == 0) sm_nrep = sqrtf(red[0]);
        __syncthreads();
        const float nrep = fmaxf(sm_nrep, 1e-12f);

        // --- Step B: cosine similarity, float4 over experts ---
        {
            const int e4 = tid & (E4N - 1);
            const int cg = tid >> 4;
            const float4* __restrict__ sim4 = (const float4*)sim;
            float4 dot = make_float4(0.f, 0.f, 0.f, 0.f);
            float4 ss  = make_float4(0.f, 0.f, 0.f, 0.f);
#pragma unroll 8
            for (int c = cg; c < CC; c += 16) {
                float4 sv = sim4[(size_t)c * E4N + e4];
                float r = rep[c];
                dot.x = fmaf(r, sv.x, dot.x); dot.y = fmaf(r, sv.y, dot.y);
                dot.z = fmaf(r, sv.z, dot.z); dot.w = fmaf(r, sv.w, dot.w);
                ss.x = fmaf(sv.x, sv.x, ss.x); ss.y = fmaf(sv.y, sv.y, ss.y);
                ss.z = fmaf(sv.z, sv.z, ss.z); ss.w = fmaf(sv.w, sv.w, ss.w);
            }
            dots[cg][e4 * 4 + 0] = dot.x; dots[cg][e4 * 4 + 1] = dot.y;
            dots[cg][e4 * 4 + 2] = dot.z; dots[cg][e4 * 4 + 3] = dot.w;
            sss[cg][e4 * 4 + 0] = ss.x; sss[cg][e4 * 4 + 1] = ss.y;
            sss[cg][e4 * 4 + 2] = ss.z; sss[cg][e4 * 4 + 3] = ss.w;
        }
        __syncthreads();

        if (tid < EE) {
            float dot = 0.f, ss = 0.f;
#pragma unroll
            for (int g = 0; g < 16; ++g) { dot += dots[g][tid]; ss += sss[g][tid]; }
            float ncol = fmaxf(sqrtf(ss), 1e-12f);
            float aff  = dot / (nrep * ncol);
            float gv   = gates[tid];
            float sig  = 1.0f / (1.0f + __expf(-gv));
            logits_s[tid] = aff - sig;
        }
        __syncthreads();

        // --- Step C: activity count ---
        if (tid == 0) {
            int na = 0;
            for (int e = 0; e < EE; ++e) na += (logits_s[e] > 0.f) ? 1 : 0;
            sm_inactive = (na == 0) ? 1 : 0;
        }
        __syncthreads();
        const int inactive = sm_inactive;

        // --- Step D: mask (hard threshold, or top-32 fallback; lax.top_k
        //     tie semantics: stable, lowest index wins among equals) ---
        if (tid < EE) {
            float l = logits_s[tid];
            float m;
            if (!inactive) {
                m = (l > 0.f) ? 1.f : 0.f;
            } else {
                int rank = 0;
                for (int j = 0; j < EE; ++j) {
                    float lj = logits_s[j];
                    rank += ((lj > l) || (lj == l && j < tid)) ? 1 : 0;
                }
                m = (rank < (EE / 2)) ? 1.f : 0.f;
            }
            msk[tid] = m;
        }
        __syncthreads();

        // --- Step E: masked softmax stats ---
        if (tid == 0) {
            float mx = -3.402823466e+38f;
            for (int e = 0; e < EE; ++e)
                if (msk[e] > 0.f) mx = fmaxf(mx, fmaxf(logits_s[e], 0.f));
            float sum = 0.f;
            for (int e = 0; e < EE; ++e)
                if (msk[e] > 0.f) sum += __expf(fmaxf(logits_s[e], 0.f) - mx);
            sm_max = mx;
            sm_sum = sum;
            if (inactive) atomicAdd(&out[FB_OFF], 1.0f);  // integer-valued -> deterministic
        }
        __syncthreads();

        // --- Step F: publish per-row results, then raise flag ---
        if (tid < EE) {
            float l = logits_s[tid];
            float gated = fmaxf(l, 0.f);
            float p = (msk[tid] > 0.f) ? (__expf(gated - sm_max) / sm_sum) : 0.f;
            g_probs_seq[b * EE + tid] = p;
            g_mask_seq[b * EE + tid]  = msk[tid];
            out[LOG_OFF + b * EE + tid] = l;
        }
        __threadfence();
        __syncthreads();
        if (tid == 0) g_flag[b] = 1;
        // msk[] already holds the mask row in smem for the broadcast below
    } else {
        // ================= consumer: wait for producer =================
        if (tid == 0) {
            while (g_flag[b] == 0) { __nanosleep(64); }
        }
        __syncthreads();
        __threadfence();
        if (tid < EE) msk[tid] = g_mask_seq[b * EE + tid];
        __syncthreads();
    }

    // ================= broadcast chunk [yc*TQ, yc*TQ+TQ) =================
    const int slot = tid & 15;   // 0..15
    const int trow = tid >> 4;   // 0..15

    const float4 pv = ((const float4*)g_probs_seq)[b * E4N + slot];

    // mask values for this slot (constant over t):
    // slot 0 -> scalars e=0,1,2,63 ; slot s>0 -> aligned float4 at e=4s-1
    float4 mv = make_float4(0.f, 0.f, 0.f, 0.f);
    float m0 = 0.f, m1 = 0.f, m2 = 0.f, m63 = 0.f;
    if (slot == 0) { m0 = msk[0]; m1 = msk[1]; m2 = msk[2]; m63 = msk[63]; }
    else { int e = 4 * slot - 1; mv = make_float4(msk[e], msk[e+1], msk[e+2], msk[e+3]); }

    const size_t brow = (size_t)b * TT * EE;
    const int t0 = yc * TQ;

#pragma unroll
    for (int it = 0; it < TQ / 16; ++it) {
        const size_t row = brow + (size_t)(t0 + it * 16 + trow) * EE;
        // probs: aligned float4 (row % 4 == 0), streaming store
        __stcs((float4*)(out) + row / 4 + slot, pv);
        // mask: base offset == 1 mod 4
        if (slot == 0) {
            float* d = out + MASK_OFF + row;
            __stcs(d + 0, m0); __stcs(d + 1, m1); __stcs(d + 2, m2); __stcs(d + 63, m63);
        } else {
            __stcs((float4*)(out + MASK_OFF + row + 4 * slot - 1), mv);
        }
    }
}

// ---------------------------------------------------------------------------
extern "C" void kernel_launch(void* const* d_in, const int* in_sizes, int n_in,
                              void* d_out, int out_size) {
    const float* hs    = (const float*)d_in[0];
    const float* sim   = (const float*)d_in[1];
    const float* gates = (const float*)d_in[2];
    float* out = (float*)d_out;

    k1_partial_sums<<<dim3(C4 / 256, BB, SEG), 256>>>(hs, out);
    k23_gating_broadcast<<<dim3(BB, TT / TQ), 256>>>(sim, gates, out);
}

// round 8
// speedup vs baseline: 1.7887x; 1.1391x over previous
#include <cuda_runtime.h>

#define BB 32
#define TT 2048
#define CC 2048
#define EE 64
#define SEG 16
#define TCHUNK (TT / SEG)          // 128
#define C4 (CC / 4)                // 512
#define E4N (EE / 4)               // 16
#define TQ 128                     // t-rows per k23 block
#define PARTS 16
#define CPART (CC / PARTS)         // 128

#define BTE (BB * TT * EE)         // 4194304 = 2^22
#define FB_OFF  BTE                // 4194304
#define LOG_OFF (BTE + 1)          // 4194305
#define MASK_OFF (BTE + 1 + BB * EE) // 4196353 (== 1 mod 4)

// Scratch (no cudaMalloc allowed)
__device__ float g_partials[SEG * BB * CC];   // 2 MB
__device__ float g_dots[BB * PARTS * EE];     // 128 KB
__device__ float g_ssum[BB * PARTS * EE];     // 128 KB
__device__ float g_sumsq[BB * PARTS];
__device__ float g_probs_seq[BB * EE];
__device__ float g_mask_seq[BB * EE];
__device__ volatile int g_flag[BB];

// ---------------------------------------------------------------------------
// Kernel 1: partial sums of hidden_states over T (split into SEG chunks).
// Measured 86% DRAM (LTS cap). __ldcs: hs is stream-once. Resets flags + FB.
// ---------------------------------------------------------------------------
__global__ void k1_partial_sums(const float* __restrict__ hs, float* __restrict__ out) {
    if (blockIdx.x == 0 && blockIdx.y == 0 && blockIdx.z == 0) {
        if (threadIdx.x == 0) out[FB_OFF] = 0.0f;
        if (threadIdx.x < BB) g_flag[threadIdx.x] = 0;
    }

    const int c4  = blockIdx.x * 256 + threadIdx.x;   // 0..511
    const int b   = blockIdx.y;
    const int seg = blockIdx.z;

    const float4* __restrict__ hs4 = (const float4*)hs;
    size_t base = ((size_t)b * TT + (size_t)seg * TCHUNK) * C4 + (size_t)c4;

    float4 acc = make_float4(0.f, 0.f, 0.f, 0.f);
#pragma unroll 8
    for (int t = 0; t < TCHUNK; ++t) {
        float4 v = __ldcs(&hs4[base + (size_t)t * C4]);
        acc.x += v.x; acc.y += v.y; acc.z += v.z; acc.w += v.w;
    }
    ((float4*)g_partials)[((size_t)seg * BB + b) * C4 + c4] = acc;
}

// ---------------------------------------------------------------------------
// Kernel 2a: stage-1 gating reduction. grid = (PARTS=16, BB=32) = 512 blocks.
// Block (part, b): reduces its 128-c chunk of g_partials -> rep chunk,
// partial sumsq, and partial dot/ss vs sim for all 64 experts.
// Deterministic fixed-order sums (no float atomics).
// ---------------------------------------------------------------------------
__global__ void k2a_partial_gating(const float* __restrict__ sim) {
    __shared__ float rep_s[CPART];
    __shared__ float red[128];
    __shared__ float dots4[4][EE];
    __shared__ float ss4[4][EE];

    const int part = blockIdx.x;
    const int b    = blockIdx.y;
    const int tid  = threadIdx.x;
    const int c0   = part * CPART;

    // rep chunk + partial sumsq
    if (tid < CPART) {
        float s = 0.f;
#pragma unroll
        for (int p = 0; p < SEG; ++p)
            s += g_partials[(size_t)p * BB * CC + (size_t)b * CC + c0 + tid];
        float r = s * (1.0f / TT);
        rep_s[tid] = r;
        red[tid] = r * r;
    }
    __syncthreads();
    for (int ofs = 64; ofs > 0; ofs >>= 1) {
        if (tid < ofs) red[tid] += red[tid + ofs];
        __syncthreads();
    }
    if (tid == 0) g_sumsq[b * PARTS + part] = red[0];

    // partial dot/ss over this c-chunk: e = tid&63, 4 c-groups of 32
    const int e  = tid & (EE - 1);
    const int cg = tid >> 6;
    float dot = 0.f, ss = 0.f;
#pragma unroll 8
    for (int j = 0; j < 32; ++j) {
        int cl = cg * 32 + j;
        float sv = sim[(size_t)(c0 + cl) * EE + e];
        dot = fmaf(rep_s[cl], sv, dot);
        ss  = fmaf(sv, sv, ss);
    }
    dots4[cg][e] = dot;
    ss4[cg][e]  = ss;
    __syncthreads();

    if (tid < EE) {
        g_dots[(size_t)(b * PARTS + part) * EE + tid] =
            dots4[0][tid] + dots4[1][tid] + dots4[2][tid] + dots4[3][tid];
        g_ssum[(size_t)(b * PARTS + part) * EE + tid] =
            ss4[0][tid] + ss4[1][tid] + ss4[2][tid] + ss4[3][tid];
    }
}

// ---------------------------------------------------------------------------
// Kernel 2b+3 fused. grid = (BB, TT/TQ) = (32, 16), 256 threads.
// Producer (b, y=0): finishes gating from 16 partials (short critical path),
// publishes flag; consumers spin briefly then broadcast. Producers are bids
// 0..31 -> wave-1 resident -> deadlock-free. Deterministic.
// ---------------------------------------------------------------------------
__global__ void k23_gating_broadcast(const float* __restrict__ gates,
                                     float* __restrict__ out) {
    __shared__ float logits_s[EE];
    __shared__ float msk[EE];
    __shared__ float sm_nrep;
    __shared__ float sm_max, sm_sum;

    const int b   = blockIdx.x;
    const int yc  = blockIdx.y;
    const int tid = threadIdx.x;

    if (yc == 0) {
        // ---- finish reductions ----
        if (tid == 0) {
            float s = 0.f;
#pragma unroll
            for (int p = 0; p < PARTS; ++p) s += g_sumsq[b * PARTS + p];
            sm_nrep = sqrtf(s);
        }
        float l = 0.f;
        if (tid < EE) {
            float dot = 0.f, ss = 0.f;
#pragma unroll
            for (int p = 0; p < PARTS; ++p) {
                dot += g_dots[(size_t)(b * PARTS + p) * EE + tid];
                ss  += g_ssum[(size_t)(b * PARTS + p) * EE + tid];
            }
            __syncthreads();   // sm_nrep ready (all threads reach below too)
            float nrep = fmaxf(sm_nrep, 1e-12f);
            float ncol = fmaxf(sqrtf(ss), 1e-12f);
            float aff  = dot / (nrep * ncol);
            float gv   = gates[tid];
            float sig  = 1.0f / (1.0f + __expf(-gv));
            l = aff - sig;
            logits_s[tid] = l;
        } else {
            __syncthreads();
        }

        // ---- activity count (hardware block-wide popcount + barrier) ----
        const int na = __syncthreads_count((tid < EE) && (l > 0.f));
        const int inactive = (na == 0) ? 1 : 0;

        // ---- mask: threshold or top-32 fallback (lax.top_k tie semantics:
        //      stable, lowest index wins among equals) ----
        if (tid < EE) {
            float m;
            if (!inactive) {
                m = (l > 0.f) ? 1.f : 0.f;
            } else {
                int rank = 0;
                for (int j = 0; j < EE; ++j) {
                    float lj = logits_s[j];
                    rank += ((lj > l) || (lj == l && j < tid)) ? 1 : 0;
                }
                m = (rank < (EE / 2)) ? 1.f : 0.f;
            }
            msk[tid] = m;
        }
        __syncthreads();

        // ---- masked softmax stats ----
        if (tid == 0) {
            float mx = -3.402823466e+38f;
            for (int e = 0; e < EE; ++e)
                if (msk[e] > 0.f) mx = fmaxf(mx, fmaxf(logits_s[e], 0.f));
            float sum = 0.f;
            for (int e = 0; e < EE; ++e)
                if (msk[e] > 0.f) sum += __expf(fmaxf(logits_s[e], 0.f) - mx);
            sm_max = mx;
            sm_sum = sum;
            if (inactive) atomicAdd(&out[FB_OFF], 1.0f);  // integer-valued -> deterministic
        }
        __syncthreads();

        // ---- publish per-row results, raise flag ----
        if (tid < EE) {
            float gated = fmaxf(l, 0.f);
            float p = (msk[tid] > 0.f) ? (__expf(gated - sm_max) / sm_sum) : 0.f;
            g_probs_seq[b * EE + tid] = p;
            g_mask_seq[b * EE + tid]  = msk[tid];
            out[LOG_OFF + b * EE + tid] = l;
        }
        __threadfence();
        __syncthreads();
        if (tid == 0) g_flag[b] = 1;
    } else {
        if (tid == 0) {
            while (g_flag[b] == 0) { __nanosleep(64); }
        }
        __syncthreads();
        __threadfence();
        if (tid < EE) msk[tid] = g_mask_seq[b * EE + tid];
        __syncthreads();
    }

    // ================= broadcast chunk [yc*TQ, yc*TQ+TQ) =================
    const int slot = tid & 15;   // 0..15
    const int trow = tid >> 4;   // 0..15

    const float4 pv = ((const float4*)g_probs_seq)[b * E4N + slot];

    // mask values per slot: slot 0 -> scalars e=0,1,2,63 ; slot s>0 ->
    // aligned float4 at e=4s-1 (MASK_OFF == 1 mod 4)
    float4 mv = make_float4(0.f, 0.f, 0.f, 0.f);
    float m0 = 0.f, m1 = 0.f, m2 = 0.f, m63 = 0.f;
    if (slot == 0) { m0 = msk[0]; m1 = msk[1]; m2 = msk[2]; m63 = msk[63]; }
    else { int e = 4 * slot - 1; mv = make_float4(msk[e], msk[e+1], msk[e+2], msk[e+3]); }

    const size_t brow = (size_t)b * TT * EE;
    const int t0 = yc * TQ;

#pragma unroll
    for (int it = 0; it < TQ / 16; ++it) {
        const size_t row = brow + (size_t)(t0 + it * 16 + trow) * EE;
        __stcs((float4*)(out) + row / 4 + slot, pv);
        if (slot == 0) {
            float* d = out + MASK_OFF + row;
            __stcs(d + 0, m0); __stcs(d + 1, m1); __stcs(d + 2, m2); __stcs(d + 63, m63);
        } else {
            __stcs((float4*)(out + MASK_OFF + row + 4 * slot - 1), mv);
        }
    }
}

// ---------------------------------------------------------------------------
extern "C" void kernel_launch(void* const* d_in, const int* in_sizes, int n_in,
                              void* d_out, int out_size) {
    const float* hs    = (const float*)d_in[0];
    const float* sim   = (const float*)d_in[1];
    const float* gates = (const float*)d_in[2];
    float* out = (float*)d_out;

    k1_partial_sums<<<dim3(C4 / 256, BB, SEG), 256>>>(hs, out);
    k2a_partial_gating<<<dim3(PARTS, BB), 256>>>(sim);
    k23_gating_broadcast<<<dim3(BB, TT / TQ), 256>>>(gates, out);
}